// round 1
// baseline (speedup 1.0000x reference)
#include <cuda_runtime.h>

#define THREADS 512
#define GROUPS 8            // 64-thread groups per block
#define PAIRS 3             // f32x2 row-pairs per group per chunk
#define ROWS_PER_CHUNK (GROUPS * PAIRS * 2)   // 48 rows / block / chunk

// ---- math constants (double-evaluated, folded) ----
// PW0 = sqrt(1/128); C0B = PW0/sqrt(3); C1 = sqrt(3/128)/sqrt(3) = PW0; C2 = sqrt(3/64)/sqrt(6)*8 = 1/sqrt(2)
#define PW0F 0.08838834764831845f
#define C0BF 0.05103103630798288f
#define C1F  0.08838834764831845f
#define C2F  0.7071067811865476f

// smem (floats): [0,20480) five 64x64 weight mats (ss, sv, vv0, vs, vv1) laid out [k*64+c];
// [20480,20544) bias; [20544, ...) x staging: per group, per chan(5), per pair(3), float2[64] over k.
#define W_FLOATS   (5 * 4096)
#define BIAS_OFF   W_FLOATS
#define XST_OFF    (W_FLOATS + 64)
#define XST_PER_G  (5 * PAIRS * 64 * 2)       // floats
#define SMEM_FLOATS (XST_OFF + GROUPS * XST_PER_G)   // 35904 floats = 143616 B

__device__ __forceinline__ unsigned long long dup2(float w) {
    unsigned int u = __float_as_uint(w);
    unsigned long long r;
    asm("mov.b64 %0, {%1, %1};" : "=l"(r) : "r"(u));
    return r;
}
__device__ __forceinline__ void fma2(unsigned long long& d, unsigned long long a, unsigned long long b) {
    asm("fma.rn.f32x2 %0, %1, %2, %0;" : "+l"(d) : "l"(a), "l"(b));
}
__device__ __forceinline__ float f2lo(unsigned long long v) { return __uint_as_float((unsigned int)v); }
__device__ __forceinline__ float f2hi(unsigned long long v) { return __uint_as_float((unsigned int)(v >> 32)); }

__global__ __launch_bounds__(THREADS, 1)
void o3tp_kernel(const float* __restrict__ x1, const float* __restrict__ x2,
                 const float* __restrict__ w_ss, const float* __restrict__ w_vv0,
                 const float* __restrict__ w_sv, const float* __restrict__ w_vs,
                 const float* __restrict__ w_vv1, const float* __restrict__ bias,
                 float* __restrict__ out, int nrows)
{
    extern __shared__ float smem[];

    // ---- cache weights + bias in smem (float4 copies) ----
    {
        const float* src[5] = { w_ss, w_sv, w_vv0, w_vs, w_vv1 };
        #pragma unroll
        for (int m = 0; m < 5; m++) {
            float4* dst4 = (float4*)(smem + m * 4096);
            const float4* src4 = (const float4*)src[m];
            for (int i = threadIdx.x; i < 1024; i += THREADS) dst4[i] = src4[i];
        }
        if (threadIdx.x < 64) smem[BIAS_OFF + threadIdx.x] = bias[threadIdx.x];
    }
    __syncthreads();

    const int g = threadIdx.x >> 6;
    const int lane64 = threadIdx.x & 63;
    const int c = lane64;

    float2* xg = (float2*)(smem + XST_OFF) + (size_t)g * (5 * PAIRS * 64);

    const float* wss  = smem;
    const float* wsv  = smem + 4096;
    const float* wvv0 = smem + 8192;
    const float* wvs  = smem + 12288;
    const float* wvv1 = smem + 16384;
    const float bconst = smem[BIAS_OFF + c];

    const int total_chunks = (nrows + ROWS_PER_CHUNK - 1) / ROWS_PER_CHUNK;

    for (int ch = blockIdx.x; ch < total_chunks; ch += gridDim.x) {
        const int base = ch * ROWS_PER_CHUNK + g * (2 * PAIRS);

        // ---- stage: thread handles k = lane64 for this group's 6 rows ----
        {
            const int k = lane64;
            #pragma unroll
            for (int p = 0; p < PAIRS; p++) {
                int r0 = base + 2 * p, r1 = r0 + 1;
                int rr0 = (r0 < nrows) ? r0 : 0;
                int rr1 = (r1 < nrows) ? r1 : 0;
                const float* row0 = x1 + (size_t)rr0 * 256;
                const float* row1 = x1 + (size_t)rr1 * 256;
                float xs0 = __ldg(row0 + k);
                float xs1 = __ldg(row1 + k);
                float a00 = __ldg(row0 + 64 + 3 * k);
                float a01 = __ldg(row0 + 65 + 3 * k);
                float a02 = __ldg(row0 + 66 + 3 * k);
                float a10 = __ldg(row1 + 64 + 3 * k);
                float a11 = __ldg(row1 + 65 + 3 * k);
                float a12 = __ldg(row1 + 66 + 3 * k);
                float4 q0 = *(const float4*)(x2 + (size_t)4 * rr0);
                float4 q1 = *(const float4*)(x2 + (size_t)4 * rr1);
                float d0 = fmaf(a00, q0.y, fmaf(a01, q0.z, a02 * q0.w));
                float d1 = fmaf(a10, q1.y, fmaf(a11, q1.z, a12 * q1.w));
                xg[(0 * PAIRS + p) * 64 + k] = make_float2(xs0, xs1);
                xg[(1 * PAIRS + p) * 64 + k] = make_float2(d0, d1);
                xg[(2 * PAIRS + p) * 64 + k] = make_float2(a00, a10);
                xg[(3 * PAIRS + p) * 64 + k] = make_float2(a01, a11);
                xg[(4 * PAIRS + p) * 64 + k] = make_float2(a02, a12);
            }
        }
        __syncthreads();

        // ---- k-loop: 9 channels x 3 pairs of f32x2 accumulators ----
        unsigned long long acc[9][PAIRS];
        #pragma unroll
        for (int q = 0; q < 9; q++)
            #pragma unroll
            for (int p = 0; p < PAIRS; p++) acc[q][p] = 0ull;

        #pragma unroll 2
        for (int k = 0; k < 64; k += 2) {
            unsigned long long dss0 = dup2(wss[k * 64 + c]),        dss1 = dup2(wss[(k + 1) * 64 + c]);
            unsigned long long dsv0 = dup2(wsv[k * 64 + c]),        dsv1 = dup2(wsv[(k + 1) * 64 + c]);
            unsigned long long dv00 = dup2(wvv0[k * 64 + c]),       dv01 = dup2(wvv0[(k + 1) * 64 + c]);
            unsigned long long dvs0 = dup2(wvs[k * 64 + c]),        dvs1 = dup2(wvs[(k + 1) * 64 + c]);
            unsigned long long dv10 = dup2(wvv1[k * 64 + c]),       dv11 = dup2(wvv1[(k + 1) * 64 + c]);
            #pragma unroll
            for (int p = 0; p < PAIRS; p++) {
                ulonglong2 xs = *(const ulonglong2*)(xg + (0 * PAIRS + p) * 64 + k);
                fma2(acc[0][p], xs.x, dss0); fma2(acc[0][p], xs.y, dss1);
                fma2(acc[1][p], xs.x, dsv0); fma2(acc[1][p], xs.y, dsv1);
                ulonglong2 dt = *(const ulonglong2*)(xg + (1 * PAIRS + p) * 64 + k);
                fma2(acc[2][p], dt.x, dv00); fma2(acc[2][p], dt.y, dv01);
                #pragma unroll
                for (int i = 0; i < 3; i++) {
                    ulonglong2 xv = *(const ulonglong2*)(xg + ((2 + i) * PAIRS + p) * 64 + k);
                    fma2(acc[3 + i][p], xv.x, dvs0); fma2(acc[3 + i][p], xv.y, dvs1);
                    fma2(acc[6 + i][p], xv.x, dv10); fma2(acc[6 + i][p], xv.y, dv11);
                }
            }
        }

        // ---- epilogue: gate, cross product, scale, store ----
        #pragma unroll
        for (int p = 0; p < PAIRS; p++) {
            #pragma unroll
            for (int h = 0; h < 2; h++) {
                int r = base + 2 * p + h;
                if (r < nrows) {
                    float ss  = h ? f2hi(acc[0][p]) : f2lo(acc[0][p]);
                    float sv  = h ? f2hi(acc[1][p]) : f2lo(acc[1][p]);
                    float vv0 = h ? f2hi(acc[2][p]) : f2lo(acc[2][p]);
                    float vs0 = h ? f2hi(acc[3][p]) : f2lo(acc[3][p]);
                    float vs1 = h ? f2hi(acc[4][p]) : f2lo(acc[4][p]);
                    float vs2 = h ? f2hi(acc[5][p]) : f2lo(acc[5][p]);
                    float a0  = h ? f2hi(acc[6][p]) : f2lo(acc[6][p]);
                    float a1  = h ? f2hi(acc[7][p]) : f2lo(acc[7][p]);
                    float a2  = h ? f2hi(acc[8][p]) : f2lo(acc[8][p]);

                    float4 q = *(const float4*)(x2 + (size_t)4 * r);
                    float x2s = q.x, v0 = q.y, v1 = q.z, v2 = q.w;

                    float o0 = fmaf(PW0F * x2s, ss, fmaf(C0BF, vv0, bconst));
                    float o10 = C1F * fmaf(sv, v0, vs0 * x2s);
                    float o11 = C1F * fmaf(sv, v1, vs1 * x2s);
                    float o12 = C1F * fmaf(sv, v2, vs2 * x2s);
                    float o20 = C2F * (a1 * v2 - a2 * v1);
                    float o21 = C2F * (a2 * v0 - a0 * v2);
                    float o22 = C2F * (a0 * v1 - a1 * v0);

                    float* o = out + (size_t)r * 448;
                    o[c] = o0;
                    o[64 + 3 * c]  = o10;
                    o[65 + 3 * c]  = o11;
                    o[66 + 3 * c]  = o12;
                    o[256 + 3 * c] = o20;
                    o[257 + 3 * c] = o21;
                    o[258 + 3 * c] = o22;
                }
            }
        }
        __syncthreads();   // protect xg reuse next chunk
    }
}

extern "C" void kernel_launch(void* const* d_in, const int* in_sizes, int n_in,
                              void* d_out, int out_size)
{
    const float* x1    = (const float*)d_in[0];
    const float* x2    = (const float*)d_in[1];
    const float* w_ss  = (const float*)d_in[2];
    const float* w_vv0 = (const float*)d_in[3];
    const float* w_sv  = (const float*)d_in[4];
    const float* w_vs  = (const float*)d_in[5];
    const float* w_vv1 = (const float*)d_in[6];
    const float* bias  = (const float*)d_in[7];

    int nrows = in_sizes[0] / 256;

    int smem_bytes = SMEM_FLOATS * (int)sizeof(float);
    cudaFuncSetAttribute(o3tp_kernel, cudaFuncAttributeMaxDynamicSharedMemorySize, smem_bytes);

    int sm_count = 148;
    cudaDeviceGetAttribute(&sm_count, cudaDevAttrMultiProcessorCount, 0);

    o3tp_kernel<<<sm_count, THREADS, smem_bytes>>>(
        x1, x2, w_ss, w_vv0, w_sv, w_vs, w_vv1, bias, (float*)d_out, nrows);
}

// round 2
// speedup vs baseline: 1.0038x; 1.0038x over previous
#include <cuda_runtime.h>

#define THREADS 512
#define GROUPS 8            // 64-thread groups per block
#define PAIRS 3             // f32x2 row-pairs per group per chunk
#define ROWS_PER_CHUNK (GROUPS * PAIRS * 2)   // 48 rows / block / chunk

// ---- math constants (double-evaluated, folded) ----
// PW0 = sqrt(1/128); C0B = PW0/sqrt(3); C1 = sqrt(3/128)/sqrt(3) = PW0; C2 = sqrt(3/64)/sqrt(6)*8 = 1/sqrt(2)
#define PW0F 0.08838834764831845f
#define C0BF 0.05103103630798288f
#define C1F  0.08838834764831845f
#define C2F  0.7071067811865476f

// smem (floats): [0,20480) five 64x64 weight mats (ss, sv, vv0, vs, vv1) laid out [k*64+c];
// [20480,20544) bias; [20544, ...) x staging: per group, per chan(5), per pair(3), float2[64] over k.
#define W_FLOATS   (5 * 4096)
#define BIAS_OFF   W_FLOATS
#define XST_OFF    (W_FLOATS + 64)
#define XST_PER_G  (5 * PAIRS * 64 * 2)       // floats
#define SMEM_FLOATS (XST_OFF + GROUPS * XST_PER_G)   // 35904 floats = 143616 B

__device__ __forceinline__ unsigned long long dup2(float w) {
    unsigned int u = __float_as_uint(w);
    unsigned long long r;
    asm("mov.b64 %0, {%1, %1};" : "=l"(r) : "r"(u));
    return r;
}
__device__ __forceinline__ void fma2(unsigned long long& d, unsigned long long a, unsigned long long b) {
    asm("fma.rn.f32x2 %0, %1, %2, %0;" : "+l"(d) : "l"(a), "l"(b));
}
__device__ __forceinline__ float f2lo(unsigned long long v) { return __uint_as_float((unsigned int)v); }
__device__ __forceinline__ float f2hi(unsigned long long v) { return __uint_as_float((unsigned int)(v >> 32)); }

__global__ __launch_bounds__(THREADS, 1)
void o3tp_kernel(const float* __restrict__ x1, const float* __restrict__ x2,
                 const float* __restrict__ w_ss, const float* __restrict__ w_vv0,
                 const float* __restrict__ w_sv, const float* __restrict__ w_vs,
                 const float* __restrict__ w_vv1, const float* __restrict__ bias,
                 float* __restrict__ out, int nrows)
{
    extern __shared__ float smem[];

    // ---- cache weights + bias in smem (float4 copies) ----
    {
        const float* src[5] = { w_ss, w_sv, w_vv0, w_vs, w_vv1 };
        #pragma unroll
        for (int m = 0; m < 5; m++) {
            float4* dst4 = (float4*)(smem + m * 4096);
            const float4* src4 = (const float4*)src[m];
            for (int i = threadIdx.x; i < 1024; i += THREADS) dst4[i] = src4[i];
        }
        if (threadIdx.x < 64) smem[BIAS_OFF + threadIdx.x] = bias[threadIdx.x];
    }
    __syncthreads();

    const int g = threadIdx.x >> 6;
    const int lane64 = threadIdx.x & 63;
    const int c = lane64;

    float2* xg = (float2*)(smem + XST_OFF) + (size_t)g * (5 * PAIRS * 64);

    const float* wss  = smem;
    const float* wsv  = smem + 4096;
    const float* wvv0 = smem + 8192;
    const float* wvs  = smem + 12288;
    const float* wvv1 = smem + 16384;
    const float bconst = smem[BIAS_OFF + c];

    const int total_chunks = (nrows + ROWS_PER_CHUNK - 1) / ROWS_PER_CHUNK;

    for (int ch = blockIdx.x; ch < total_chunks; ch += gridDim.x) {
        const int base = ch * ROWS_PER_CHUNK + g * (2 * PAIRS);

        // ---- stage: thread handles k = lane64 for this group's 6 rows ----
        {
            const int k = lane64;
            #pragma unroll
            for (int p = 0; p < PAIRS; p++) {
                int r0 = base + 2 * p, r1 = r0 + 1;
                int rr0 = (r0 < nrows) ? r0 : 0;
                int rr1 = (r1 < nrows) ? r1 : 0;
                const float* row0 = x1 + (size_t)rr0 * 256;
                const float* row1 = x1 + (size_t)rr1 * 256;
                float xs0 = __ldg(row0 + k);
                float xs1 = __ldg(row1 + k);
                float a00 = __ldg(row0 + 64 + 3 * k);
                float a01 = __ldg(row0 + 65 + 3 * k);
                float a02 = __ldg(row0 + 66 + 3 * k);
                float a10 = __ldg(row1 + 64 + 3 * k);
                float a11 = __ldg(row1 + 65 + 3 * k);
                float a12 = __ldg(row1 + 66 + 3 * k);
                float4 q0 = *(const float4*)(x2 + (size_t)4 * rr0);
                float4 q1 = *(const float4*)(x2 + (size_t)4 * rr1);
                float d0 = fmaf(a00, q0.y, fmaf(a01, q0.z, a02 * q0.w));
                float d1 = fmaf(a10, q1.y, fmaf(a11, q1.z, a12 * q1.w));
                xg[(0 * PAIRS + p) * 64 + k] = make_float2(xs0, xs1);
                xg[(1 * PAIRS + p) * 64 + k] = make_float2(d0, d1);
                xg[(2 * PAIRS + p) * 64 + k] = make_float2(a00, a10);
                xg[(3 * PAIRS + p) * 64 + k] = make_float2(a01, a11);
                xg[(4 * PAIRS + p) * 64 + k] = make_float2(a02, a12);
            }
        }
        __syncthreads();

        // ---- k-loop: 9 channels x 3 pairs of f32x2 accumulators ----
        unsigned long long acc[9][PAIRS];
        #pragma unroll
        for (int q = 0; q < 9; q++)
            #pragma unroll
            for (int p = 0; p < PAIRS; p++) acc[q][p] = 0ull;

        #pragma unroll 2
        for (int k = 0; k < 64; k += 2) {
            unsigned long long dss0 = dup2(wss[k * 64 + c]),        dss1 = dup2(wss[(k + 1) * 64 + c]);
            unsigned long long dsv0 = dup2(wsv[k * 64 + c]),        dsv1 = dup2(wsv[(k + 1) * 64 + c]);
            unsigned long long dv00 = dup2(wvv0[k * 64 + c]),       dv01 = dup2(wvv0[(k + 1) * 64 + c]);
            unsigned long long dvs0 = dup2(wvs[k * 64 + c]),        dvs1 = dup2(wvs[(k + 1) * 64 + c]);
            unsigned long long dv10 = dup2(wvv1[k * 64 + c]),       dv11 = dup2(wvv1[(k + 1) * 64 + c]);
            #pragma unroll
            for (int p = 0; p < PAIRS; p++) {
                ulonglong2 xs = *(const ulonglong2*)(xg + (0 * PAIRS + p) * 64 + k);
                fma2(acc[0][p], xs.x, dss0); fma2(acc[0][p], xs.y, dss1);
                fma2(acc[1][p], xs.x, dsv0); fma2(acc[1][p], xs.y, dsv1);
                ulonglong2 dt = *(const ulonglong2*)(xg + (1 * PAIRS + p) * 64 + k);
                fma2(acc[2][p], dt.x, dv00); fma2(acc[2][p], dt.y, dv01);
                #pragma unroll
                for (int i = 0; i < 3; i++) {
                    ulonglong2 xv = *(const ulonglong2*)(xg + ((2 + i) * PAIRS + p) * 64 + k);
                    fma2(acc[3 + i][p], xv.x, dvs0); fma2(acc[3 + i][p], xv.y, dvs1);
                    fma2(acc[6 + i][p], xv.x, dv10); fma2(acc[6 + i][p], xv.y, dv11);
                }
            }
        }

        // ---- epilogue: gate, cross product, scale, store ----
        #pragma unroll
        for (int p = 0; p < PAIRS; p++) {
            #pragma unroll
            for (int h = 0; h < 2; h++) {
                int r = base + 2 * p + h;
                if (r < nrows) {
                    float ss  = h ? f2hi(acc[0][p]) : f2lo(acc[0][p]);
                    float sv  = h ? f2hi(acc[1][p]) : f2lo(acc[1][p]);
                    float vv0 = h ? f2hi(acc[2][p]) : f2lo(acc[2][p]);
                    float vs0 = h ? f2hi(acc[3][p]) : f2lo(acc[3][p]);
                    float vs1 = h ? f2hi(acc[4][p]) : f2lo(acc[4][p]);
                    float vs2 = h ? f2hi(acc[5][p]) : f2lo(acc[5][p]);
                    float a0  = h ? f2hi(acc[6][p]) : f2lo(acc[6][p]);
                    float a1  = h ? f2hi(acc[7][p]) : f2lo(acc[7][p]);
                    float a2  = h ? f2hi(acc[8][p]) : f2lo(acc[8][p]);

                    float4 q = *(const float4*)(x2 + (size_t)4 * r);
                    float x2s = q.x, v0 = q.y, v1 = q.z, v2 = q.w;

                    float o0 = fmaf(PW0F * x2s, ss, fmaf(C0BF, vv0, bconst));
                    float o10 = C1F * fmaf(sv, v0, vs0 * x2s);
                    float o11 = C1F * fmaf(sv, v1, vs1 * x2s);
                    float o12 = C1F * fmaf(sv, v2, vs2 * x2s);
                    float o20 = C2F * (a1 * v2 - a2 * v1);
                    float o21 = C2F * (a2 * v0 - a0 * v2);
                    float o22 = C2F * (a0 * v1 - a1 * v0);

                    float* o = out + (size_t)r * 448;
                    o[c] = o0;
                    o[64 + 3 * c]  = o10;
                    o[65 + 3 * c]  = o11;
                    o[66 + 3 * c]  = o12;
                    o[256 + 3 * c] = o20;
                    o[257 + 3 * c] = o21;
                    o[258 + 3 * c] = o22;
                }
            }
        }
        __syncthreads();   // protect xg reuse next chunk
    }
}

extern "C" void kernel_launch(void* const* d_in, const int* in_sizes, int n_in,
                              void* d_out, int out_size)
{
    const float* x1    = (const float*)d_in[0];
    const float* x2    = (const float*)d_in[1];
    const float* w_ss  = (const float*)d_in[2];
    const float* w_vv0 = (const float*)d_in[3];
    const float* w_sv  = (const float*)d_in[4];
    const float* w_vs  = (const float*)d_in[5];
    const float* w_vv1 = (const float*)d_in[6];
    const float* bias  = (const float*)d_in[7];

    int nrows = in_sizes[0] / 256;

    int smem_bytes = SMEM_FLOATS * (int)sizeof(float);
    cudaFuncSetAttribute(o3tp_kernel, cudaFuncAttributeMaxDynamicSharedMemorySize, smem_bytes);

    int sm_count = 148;
    cudaDeviceGetAttribute(&sm_count, cudaDevAttrMultiProcessorCount, 0);

    o3tp_kernel<<<sm_count, THREADS, smem_bytes>>>(
        x1, x2, w_ss, w_vv0, w_sv, w_vs, w_vv1, bias, (float*)d_out, nrows);
}

// round 4
// speedup vs baseline: 1.6908x; 1.6844x over previous
#include <cuda_runtime.h>
#include <cuda_bf16.h>
#include <cstdint>

#define THREADS 256
#define TILE_M 32

// ---- folded constants ----
#define PW0F 0.08838834764831845f   // sqrt(1/128)
#define C0BF 0.05103103630798288f   // PW0/sqrt(3)
#define C1F  0.08838834764831845f   // sqrt(3/128)/sqrt(3) = PW0
#define C2F  0.7071067811865476f    // sqrt(3/64)/sqrt(6)*8 = 1/sqrt(2)

// ---- smem layout (byte offsets) ----
// Weights: 10 tiles (5 mats x hi/lo), each [64k x 64n] bf16, row=128B, XOR-swizzled.
#define SM_W     0
#define SM_A     81920      // 8 half-buffers (xs,a0,a1,a2 x hi/lo), each [32r x 64k] bf16 = 4096B
#define SM_X2    114688     // 32 * float4
#define SM_BIAS  115200     // 64 * f32
#define SM_STG   115456     // 32 rows * 452 f32 stage
#define STG_STRIDE 452
#define SM_TOTAL 173312

#define SWZ(o) ((o) ^ (((o) >> 3) & 0x70))

// ================= helpers =================
static __device__ __forceinline__ uint32_t smem_u32(const void* p) {
    uint32_t a;
    asm("{ .reg .u64 t; cvta.to.shared.u64 t, %1; cvt.u32.u64 %0, t; }" : "=r"(a) : "l"(p));
    return a;
}
static __device__ __forceinline__ void ldsm4(uint32_t* r, uint32_t addr) {
    asm volatile("ldmatrix.sync.aligned.m8n8.x4.shared.b16 {%0,%1,%2,%3}, [%4];"
                 : "=r"(r[0]), "=r"(r[1]), "=r"(r[2]), "=r"(r[3]) : "r"(addr));
}
static __device__ __forceinline__ void ldsm4t(uint32_t* r, uint32_t addr) {
    asm volatile("ldmatrix.sync.aligned.m8n8.x4.trans.shared.b16 {%0,%1,%2,%3}, [%4];"
                 : "=r"(r[0]), "=r"(r[1]), "=r"(r[2]), "=r"(r[3]) : "r"(addr));
}
static __device__ __forceinline__ void mma16816(float* d, const uint32_t* a, uint32_t b0, uint32_t b1) {
    asm volatile("mma.sync.aligned.m16n8k16.row.col.f32.bf16.bf16.f32 "
                 "{%0,%1,%2,%3}, {%4,%5,%6,%7}, {%8,%9}, {%0,%1,%2,%3};"
                 : "+f"(d[0]), "+f"(d[1]), "+f"(d[2]), "+f"(d[3])
                 : "r"(a[0]), "r"(a[1]), "r"(a[2]), "r"(a[3]), "r"(b0), "r"(b1));
}
// 3-pass bf16-split product accumulate into d[2][4] (two n8 tiles)
static __device__ __forceinline__ void dualmma(float d[2][4], const uint32_t* ah, const uint32_t* al,
                                               const uint32_t* Bh, const uint32_t* Bl) {
    #pragma unroll
    for (int nb = 0; nb < 2; nb++) {
        mma16816(d[nb], ah, Bh[2 * nb], Bh[2 * nb + 1]);
        mma16816(d[nb], al, Bh[2 * nb], Bh[2 * nb + 1]);
        mma16816(d[nb], ah, Bl[2 * nb], Bl[2 * nb + 1]);
    }
}
// split fp32 pair -> bf16 hi/lo tiles at swizzled offset
static __device__ __forceinline__ void put_pair(char* smem, uint32_t hi_off, uint32_t lo_off,
                                                uint32_t off, float v0, float v1) {
    __nv_bfloat16 h0 = __float2bfloat16(v0);
    __nv_bfloat16 h1 = __float2bfloat16(v1);
    __nv_bfloat16 l0 = __float2bfloat16(v0 - __bfloat162float(h0));
    __nv_bfloat16 l1 = __float2bfloat16(v1 - __bfloat162float(h1));
    uint32_t hp = (uint32_t)__bfloat16_as_ushort(h0) | ((uint32_t)__bfloat16_as_ushort(h1) << 16);
    uint32_t lp = (uint32_t)__bfloat16_as_ushort(l0) | ((uint32_t)__bfloat16_as_ushort(l1) << 16);
    uint32_t so = SWZ(off);
    *(uint32_t*)(smem + hi_off + so) = hp;
    *(uint32_t*)(smem + lo_off + so) = lp;
}

__global__ __launch_bounds__(THREADS, 1)
void o3tp_mma_kernel(const float* __restrict__ x1, const float* __restrict__ x2,
                     const float* __restrict__ w_ss, const float* __restrict__ w_vv0,
                     const float* __restrict__ w_sv, const float* __restrict__ w_vs,
                     const float* __restrict__ w_vv1, const float* __restrict__ bias,
                     float* __restrict__ out, int nrows)
{
    extern __shared__ char smem[];
    const int tid = threadIdx.x;
    const int lane = tid & 31;
    const int wid = tid >> 5;
    const int rq = wid & 1;        // row block: rows 16*rq .. +16
    const int nh = wid >> 1;       // col block: cols 16*nh .. +16
    const uint32_t smb = smem_u32(smem);

    // ---- weight prep: [k][n] bf16 hi/lo, swizzled; order Wss, Wsv, Wvv0, Wvs, Wvv1 ----
    {
        const float* wsrc[5] = { w_ss, w_sv, w_vv0, w_vs, w_vv1 };
        #pragma unroll
        for (int m = 0; m < 5; m++) {
            uint32_t hi_off = SM_W + (uint32_t)(2 * m) * 8192;
            uint32_t lo_off = hi_off + 8192;
            #pragma unroll
            for (int it = 0; it < 8; it++) {
                int idx = it * THREADS + tid;         // 0..2047
                int k = idx >> 5, np = idx & 31;
                float2 w2 = *(const float2*)(wsrc[m] + k * 64 + 2 * np);
                put_pair(smem, hi_off, lo_off, (uint32_t)(k * 128 + np * 4), w2.x, w2.y);
            }
        }
        if (tid < 64) *(float*)(smem + SM_BIAS + tid * 4) = bias[tid];
    }
    __syncthreads();

    // ---- per-lane constant address pieces ----
    const int t4 = lane >> 3;
    const int arow = 16 * rq + ((t4 & 1) << 3) + (lane & 7);
    const uint32_t a_rb  = (uint32_t)arow * 128;
    const uint32_t a_kx  = (uint32_t)(arow & 7) << 4;
    const uint32_t a_kb0 = (uint32_t)(t4 >> 1) << 4;
    const int brow_l = ((t4 & 1) << 3) + (lane & 7);
    const uint32_t b_cb = (uint32_t)(2 * (16 * nh + ((t4 >> 1) << 3)));
    const uint32_t b_kx = (uint32_t)(lane & 7) << 4;

    const int ntiles = (nrows + TILE_M - 1) / TILE_M;
    const int g = lane >> 2, tq = lane & 3;
    float* stg = (float*)(smem + SM_STG);
    const float* bias_s = (const float*)(smem + SM_BIAS);

    for (int tile = blockIdx.x; tile < ntiles; tile += gridDim.x) {
        const int row0 = tile * TILE_M;

        // ---- stage x2 rows ----
        if (tid < 32) {
            int rg = row0 + tid; if (rg >= nrows) rg = nrows - 1;
            *(float4*)(smem + SM_X2 + tid * 16) = *(const float4*)(x2 + (size_t)4 * rg);
        }

        // ---- build 4 base A matrices (xs, a0, a1, a2), bf16 hi/lo ----
        #pragma unroll
        for (int it = 0; it < 4; it++) {
            int idx = it * THREADS + tid;            // 0..1023
            int row = idx >> 5, kp = idx & 31;
            int rg = row0 + row; if (rg >= nrows) rg = nrows - 1;
            const float* xr = x1 + (size_t)rg * 256;
            float2 xs = *(const float2*)(xr + 2 * kp);
            float2 f0 = *(const float2*)(xr + 64 + 6 * kp);
            float2 f1 = *(const float2*)(xr + 66 + 6 * kp);
            float2 f2 = *(const float2*)(xr + 68 + 6 * kp);
            uint32_t off = (uint32_t)(row * 128 + kp * 4);
            put_pair(smem, SM_A + 0 * 4096, SM_A + 1 * 4096, off, xs.x, xs.y);   // xs
            put_pair(smem, SM_A + 2 * 4096, SM_A + 3 * 4096, off, f0.x, f1.y);   // a0 (k, k+1)
            put_pair(smem, SM_A + 4 * 4096, SM_A + 5 * 4096, off, f0.y, f2.x);   // a1
            put_pair(smem, SM_A + 6 * 4096, SM_A + 7 * 4096, off, f1.x, f2.y);   // a2
        }
        __syncthreads();

        // ---- 11 GEMMs: d[0]=Yss d[1]=Ysv d[2..4]=a_j@Wvv0 d[5..7]=a_j@Wvs d[8..10]=a_j@Wvv1 ----
        float d[11][2][4];
        #pragma unroll
        for (int q = 0; q < 11; q++)
            #pragma unroll
            for (int nb = 0; nb < 2; nb++)
                #pragma unroll
                for (int e = 0; e < 4; e++) d[q][nb][e] = 0.0f;

        #pragma unroll
        for (int ks = 0; ks < 4; ks++) {
            uint32_t Ah[4][4], Al[4][4];
            #pragma unroll
            for (int am = 0; am < 4; am++) {
                uint32_t ab = smb + SM_A + (uint32_t)(2 * am) * 4096 + a_rb + ((32u * ks + a_kb0) ^ a_kx);
                ldsm4(Ah[am], ab);
                ldsm4(Al[am], ab + 4096);
            }
            #pragma unroll
            for (int wm = 0; wm < 5; wm++) {
                uint32_t bb = smb + SM_W + (uint32_t)(2 * wm) * 8192
                            + (uint32_t)(16 * ks + brow_l) * 128 + (b_cb ^ b_kx);
                uint32_t Bh[4], Bl[4];
                ldsm4t(Bh, bb);
                ldsm4t(Bl, bb + 8192);
                if (wm == 0)      dualmma(d[0], Ah[0], Al[0], Bh, Bl);
                else if (wm == 1) dualmma(d[1], Ah[0], Al[0], Bh, Bl);
                else {
                    #pragma unroll
                    for (int j = 0; j < 3; j++)
                        dualmma(d[2 + (wm - 2) * 3 + j], Ah[1 + j], Al[1 + j], Bh, Bl);
                }
            }
        }

        // ---- epilogue: per-row scalar gating + dot + cross in registers, stage interleaved ----
        #pragma unroll
        for (int h = 0; h < 2; h++) {
            int r = 16 * rq + g + 8 * h;
            float4 q = *(const float4*)(smem + SM_X2 + r * 16);
            float x2s = q.x, v0 = q.y, v1 = q.z, v2 = q.w;
            float* sr = stg + r * STG_STRIDE;
            #pragma unroll
            for (int nt = 0; nt < 2; nt++) {
                #pragma unroll
                for (int e = 0; e < 2; e++) {
                    int cc = 16 * nh + 8 * nt + 2 * tq + e;
                    int ri = 2 * h + e;
                    float Yss = d[0][nt][ri], Ysv = d[1][nt][ri];
                    float Y00 = d[2][nt][ri], Y01 = d[3][nt][ri], Y02 = d[4][nt][ri];
                    float Yv0 = d[5][nt][ri], Yv1 = d[6][nt][ri], Yv2 = d[7][nt][ri];
                    float Yw0 = d[8][nt][ri], Yw1 = d[9][nt][ri], Yw2 = d[10][nt][ri];

                    float dotY = fmaf(v0, Y00, fmaf(v1, Y01, v2 * Y02));
                    sr[cc] = fmaf(PW0F * x2s, Yss, fmaf(C0BF, dotY, bias_s[cc]));
                    sr[64 + 3 * cc + 0] = C1F * fmaf(v0, Ysv, x2s * Yv0);
                    sr[64 + 3 * cc + 1] = C1F * fmaf(v1, Ysv, x2s * Yv1);
                    sr[64 + 3 * cc + 2] = C1F * fmaf(v2, Ysv, x2s * Yv2);
                    sr[256 + 3 * cc + 0] = C2F * (Yw1 * v2 - Yw2 * v1);
                    sr[256 + 3 * cc + 1] = C2F * (Yw2 * v0 - Yw0 * v2);
                    sr[256 + 3 * cc + 2] = C2F * (Yw0 * v1 - Yw1 * v0);
                }
            }
        }
        __syncthreads();

        // ---- coalesced copy-out: 32 rows x 448 f32 ----
        #pragma unroll
        for (int i = 0; i < 14; i++) {
            int f = i * THREADS + tid;               // < 3584
            int r = f / 112, j = (f % 112) * 4;
            float4 v = *(const float4*)(stg + r * STG_STRIDE + j);
            int rg = row0 + r;
            if (rg < nrows) *(float4*)(out + (size_t)rg * 448 + j) = v;
        }
    }
}

extern "C" void kernel_launch(void* const* d_in, const int* in_sizes, int n_in,
                              void* d_out, int out_size)
{
    const float* x1    = (const float*)d_in[0];
    const float* x2    = (const float*)d_in[1];
    const float* w_ss  = (const float*)d_in[2];
    const float* w_vv0 = (const float*)d_in[3];
    const float* w_sv  = (const float*)d_in[4];
    const float* w_vs  = (const float*)d_in[5];
    const float* w_vv1 = (const float*)d_in[6];
    const float* bias  = (const float*)d_in[7];

    int nrows = in_sizes[0] / 256;
    int ntiles = (nrows + TILE_M - 1) / TILE_M;

    cudaFuncSetAttribute(o3tp_mma_kernel, cudaFuncAttributeMaxDynamicSharedMemorySize, SM_TOTAL);

    int sm_count = 148;
    cudaDeviceGetAttribute(&sm_count, cudaDevAttrMultiProcessorCount, 0);
    int grid = sm_count < ntiles ? sm_count : ntiles;
    if (grid < 1) grid = 1;

    o3tp_mma_kernel<<<grid, THREADS, SM_TOTAL>>>(
        x1, x2, w_ss, w_vv0, w_sv, w_vs, w_vv1, bias, (float*)d_out, nrows);
}

// round 6
// speedup vs baseline: 1.8619x; 1.1012x over previous
#include <cuda_runtime.h>
#include <cuda_bf16.h>
#include <cstdint>

#define THREADS 512
#define TILE_M 64

// ---- folded constants ----
#define PW0F 0.08838834764831845f   // sqrt(1/128)
#define C0BF 0.05103103630798288f   // PW0/sqrt(3)
#define C1F  0.08838834764831845f   // sqrt(3/128)/sqrt(3) = PW0
#define C2F  0.7071067811865476f    // sqrt(3/64)/sqrt(6)*8 = 1/sqrt(2)

// ---- smem layout (byte offsets) ----
// Weights: 10 tiles (5 mats x hi/lo), each [64k x 64n] bf16, 128B rows, XOR-swizzled.
//   order: 0=Wss 1=Wvv0 2=Wsv 3=Wvs 4=Wvv1
// A: 12 buffers (6 channels x hi/lo), each [64r x 64k] bf16 = 8192B.
//   channels: 0=PW0*x2s*xs  1=C0B*dot  2=xs  3=a0  4=a1  5=a2
// Stage (epilogue, 32 rows x 452 f32 = 57856B) overlaps the A region.
#define SM_W     0
#define SM_A     81920
#define SM_X2    180224     // 64 * float4
#define SM_BIAS  181248     // 64 * f32
#define SM_TOTAL 181504
#define STG_STRIDE 452

#define SWZ(o) ((o) ^ (((o) >> 3) & 0x70))

// ================= helpers =================
static __device__ __forceinline__ uint32_t smem_u32(const void* p) {
    uint32_t a;
    asm("{ .reg .u64 t; cvta.to.shared.u64 t, %1; cvt.u32.u64 %0, t; }" : "=r"(a) : "l"(p));
    return a;
}
static __device__ __forceinline__ void ldsm4(uint32_t* r, uint32_t addr) {
    asm volatile("ldmatrix.sync.aligned.m8n8.x4.shared.b16 {%0,%1,%2,%3}, [%4];"
                 : "=r"(r[0]), "=r"(r[1]), "=r"(r[2]), "=r"(r[3]) : "r"(addr));
}
static __device__ __forceinline__ void ldsm4t(uint32_t* r, uint32_t addr) {
    asm volatile("ldmatrix.sync.aligned.m8n8.x4.trans.shared.b16 {%0,%1,%2,%3}, [%4];"
                 : "=r"(r[0]), "=r"(r[1]), "=r"(r[2]), "=r"(r[3]) : "r"(addr));
}
static __device__ __forceinline__ void mma16816(float* d, const uint32_t* a, uint32_t b0, uint32_t b1) {
    asm volatile("mma.sync.aligned.m16n8k16.row.col.f32.bf16.bf16.f32 "
                 "{%0,%1,%2,%3}, {%4,%5,%6,%7}, {%8,%9}, {%0,%1,%2,%3};"
                 : "+f"(d[0]), "+f"(d[1]), "+f"(d[2]), "+f"(d[3])
                 : "r"(a[0]), "r"(a[1]), "r"(a[2]), "r"(a[3]), "r"(b0), "r"(b1));
}
// 3-pass bf16-split product accumulate into d[2][4] (two n8 tiles)
static __device__ __forceinline__ void dualmma(float d[2][4], const uint32_t* ah, const uint32_t* al,
                                               const uint32_t* Bh, const uint32_t* Bl) {
    #pragma unroll
    for (int nb = 0; nb < 2; nb++) {
        mma16816(d[nb], ah, Bh[2 * nb], Bh[2 * nb + 1]);
        mma16816(d[nb], al, Bh[2 * nb], Bh[2 * nb + 1]);
        mma16816(d[nb], ah, Bl[2 * nb], Bl[2 * nb + 1]);
    }
}
// split fp32 pair -> bf16 hi/lo at swizzled offset
static __device__ __forceinline__ void put_pair(char* smem, uint32_t hi_off, uint32_t lo_off,
                                                uint32_t off, float v0, float v1) {
    __nv_bfloat16 h0 = __float2bfloat16(v0);
    __nv_bfloat16 h1 = __float2bfloat16(v1);
    __nv_bfloat16 l0 = __float2bfloat16(v0 - __bfloat162float(h0));
    __nv_bfloat16 l1 = __float2bfloat16(v1 - __bfloat162float(h1));
    uint32_t hp = (uint32_t)__bfloat16_as_ushort(h0) | ((uint32_t)__bfloat16_as_ushort(h1) << 16);
    uint32_t lp = (uint32_t)__bfloat16_as_ushort(l0) | ((uint32_t)__bfloat16_as_ushort(l1) << 16);
    uint32_t so = SWZ(off);
    *(uint32_t*)(smem + hi_off + so) = hp;
    *(uint32_t*)(smem + lo_off + so) = lp;
}

__global__ __launch_bounds__(THREADS, 1)
void o3tp_mma2_kernel(const float* __restrict__ x1, const float* __restrict__ x2,
                      const float* __restrict__ w_ss, const float* __restrict__ w_vv0,
                      const float* __restrict__ w_sv, const float* __restrict__ w_vs,
                      const float* __restrict__ w_vv1, const float* __restrict__ bias,
                      float* __restrict__ out, int nrows)
{
    extern __shared__ char smem[];
    const int tid = threadIdx.x;
    const int lane = tid & 31;
    const int wid = tid >> 5;
    const int rq = wid & 3;        // row block: rows 16*rq .. +16 (of 64)
    const int nh = wid >> 2;       // col block: cols 16*nh .. +16
    const uint32_t smb = smem_u32(smem);

    // ---- weight prep: [k][n] bf16 hi/lo, swizzled ----
    {
        const float* wsrc[5] = { w_ss, w_vv0, w_sv, w_vs, w_vv1 };
        #pragma unroll
        for (int m = 0; m < 5; m++) {
            uint32_t hi_off = SM_W + (uint32_t)(2 * m) * 8192;
            uint32_t lo_off = hi_off + 8192;
            #pragma unroll
            for (int it = 0; it < 4; it++) {
                int idx = it * THREADS + tid;         // 0..2047
                int k = idx >> 5, np = idx & 31;
                float2 w2 = *(const float2*)(wsrc[m] + k * 64 + 2 * np);
                put_pair(smem, hi_off, lo_off, (uint32_t)(k * 128 + np * 4), w2.x, w2.y);
            }
        }
        if (tid < 64) *(float*)(smem + SM_BIAS + tid * 4) = bias[tid];
    }
    __syncthreads();

    // ---- per-lane constant address pieces (validated in R3) ----
    const int t4 = lane >> 3;
    const int arow = 16 * rq + ((t4 & 1) << 3) + (lane & 7);
    const uint32_t a_rb  = (uint32_t)arow * 128;
    const uint32_t a_kx  = (uint32_t)(arow & 7) << 4;
    const uint32_t a_kb0 = (uint32_t)(t4 >> 1) << 4;
    const int brow_l = ((t4 & 1) << 3) + (lane & 7);
    const uint32_t b_cb = (uint32_t)(2 * (16 * nh + ((t4 >> 1) << 3)));
    const uint32_t b_kx = (uint32_t)(lane & 7) << 4;

    const int ntiles = (nrows + TILE_M - 1) / TILE_M;
    const int g = lane >> 2, tq = lane & 3;
    float* stg = (float*)(smem + SM_A);               // stage overlaps A region
    const float* bias_s = (const float*)(smem + SM_BIAS);

    for (int tile = blockIdx.x; tile < ntiles; tile += gridDim.x) {
        const int row0 = tile * TILE_M;

        // ---- stage x2 rows ----
        if (tid < 64) {
            int rg = row0 + tid; if (rg >= nrows) rg = nrows - 1;
            *(float4*)(smem + SM_X2 + tid * 16) = *(const float4*)(x2 + (size_t)4 * rg);
        }
        __syncthreads();   // build below consumes SM_X2 (was the R4 race)

        // ---- build 6 A channels, bf16 hi/lo ----
        #pragma unroll
        for (int it = 0; it < 4; it++) {
            int idx = it * THREADS + tid;            // 0..2047
            int row = idx >> 5, kp = idx & 31;
            int rg = row0 + row; if (rg >= nrows) rg = nrows - 1;
            const float* xr = x1 + (size_t)rg * 256;
            float2 xs = *(const float2*)(xr + 2 * kp);
            float2 f0 = *(const float2*)(xr + 64 + 6 * kp);
            float2 f1 = *(const float2*)(xr + 66 + 6 * kp);
            float2 f2 = *(const float2*)(xr + 68 + 6 * kp);
            float4 q = *(const float4*)(smem + SM_X2 + row * 16);
            uint32_t off = (uint32_t)(row * 128 + kp * 4);
            // ch0: pre-gated scalar path
            float sc = PW0F * q.x;
            put_pair(smem, SM_A + 0 * 8192, SM_A + 1 * 8192, off, sc * xs.x, sc * xs.y);
            // ch1: pre-gated dot channel
            float d0 = fmaf(f0.x, q.y, fmaf(f0.y, q.z, f1.x * q.w));
            float d1 = fmaf(f1.y, q.y, fmaf(f2.x, q.z, f2.y * q.w));
            put_pair(smem, SM_A + 2 * 8192, SM_A + 3 * 8192, off, C0BF * d0, C0BF * d1);
            // ch2: raw xs ; ch3-5: a components (k, k+1)
            put_pair(smem, SM_A + 4 * 8192,  SM_A + 5 * 8192,  off, xs.x, xs.y);
            put_pair(smem, SM_A + 6 * 8192,  SM_A + 7 * 8192,  off, f0.x, f1.y);
            put_pair(smem, SM_A + 8 * 8192,  SM_A + 9 * 8192,  off, f0.y, f2.x);
            put_pair(smem, SM_A + 10 * 8192, SM_A + 11 * 8192, off, f1.x, f2.y);
        }
        __syncthreads();

        // ---- GEMMs: d0=out0(merged) d1=Ysv d2-4=Yv_i(@Wvs) d5-7=Yw_i(@Wvv1) ----
        float d[8][2][4];
        #pragma unroll
        for (int q8 = 0; q8 < 8; q8++)
            #pragma unroll
            for (int nb = 0; nb < 2; nb++)
                #pragma unroll
                for (int e = 0; e < 4; e++) d[q8][nb][e] = 0.0f;

        #pragma unroll
        for (int ks = 0; ks < 4; ks++) {
            const uint32_t a_koff = (32u * ks + a_kb0) ^ a_kx;
            const uint32_t b_base = (uint32_t)(16 * ks + brow_l) * 128 + (b_cb ^ b_kx);
            uint32_t Ah[4], Al[4], Bh[4], Bl[4];

            // ch0 @ Wss -> d0
            {
                uint32_t ab = smb + SM_A + 0 * 8192 + a_rb + a_koff;
                ldsm4(Ah, ab); ldsm4(Al, ab + 8192);
                uint32_t bb = smb + SM_W + 0 * 8192 + b_base;
                ldsm4t(Bh, bb); ldsm4t(Bl, bb + 8192);
                dualmma(d[0], Ah, Al, Bh, Bl);
            }
            // ch1 @ Wvv0 -> d0
            {
                uint32_t ab = smb + SM_A + 2 * 8192 + a_rb + a_koff;
                ldsm4(Ah, ab); ldsm4(Al, ab + 8192);
                uint32_t bb = smb + SM_W + 2 * 8192 + b_base;
                ldsm4t(Bh, bb); ldsm4t(Bl, bb + 8192);
                dualmma(d[0], Ah, Al, Bh, Bl);
            }
            // ch2 @ Wsv -> d1
            {
                uint32_t ab = smb + SM_A + 4 * 8192 + a_rb + a_koff;
                ldsm4(Ah, ab); ldsm4(Al, ab + 8192);
                uint32_t bb = smb + SM_W + 4 * 8192 + b_base;
                ldsm4t(Bh, bb); ldsm4t(Bl, bb + 8192);
                dualmma(d[1], Ah, Al, Bh, Bl);
            }
            // hold Wvs / Wvv1 frags, loop a-channels
            uint32_t Vh[4], Vl[4], Wh[4], Wl[4];
            {
                uint32_t bb = smb + SM_W + 6 * 8192 + b_base;
                ldsm4t(Vh, bb); ldsm4t(Vl, bb + 8192);
                bb = smb + SM_W + 8 * 8192 + b_base;
                ldsm4t(Wh, bb); ldsm4t(Wl, bb + 8192);
            }
            #pragma unroll
            for (int j = 0; j < 3; j++) {
                uint32_t ab = smb + SM_A + (uint32_t)(6 + 2 * j) * 8192 + a_rb + a_koff;
                ldsm4(Ah, ab); ldsm4(Al, ab + 8192);
                dualmma(d[2 + j], Ah, Al, Vh, Vl);
                dualmma(d[5 + j], Ah, Al, Wh, Wl);
            }
        }
        __syncthreads();   // A reads done; stage region reusable

        // ---- epilogue in two 32-row halves (stage overlaps A) ----
        #pragma unroll 1
        for (int half = 0; half < 2; half++) {
            if ((rq >> 1) == half) {
                #pragma unroll
                for (int hh = 0; hh < 2; hh++) {
                    int rl = 16 * (rq & 1) + g + 8 * hh;          // 0..31 local
                    int rt = 32 * half + rl;                       // 0..63 in tile
                    float4 q = *(const float4*)(smem + SM_X2 + rt * 16);
                    float x2s = q.x, v0 = q.y, v1 = q.z, v2 = q.w;
                    float* sr = stg + rl * STG_STRIDE;
                    #pragma unroll
                    for (int nt = 0; nt < 2; nt++) {
                        #pragma unroll
                        for (int e = 0; e < 2; e++) {
                            int cc = 16 * nh + 8 * nt + 2 * tq + e;
                            int ri = 2 * hh + e;
                            float O0  = d[0][nt][ri];
                            float Ysv = d[1][nt][ri];
                            float Yv0 = d[2][nt][ri], Yv1 = d[3][nt][ri], Yv2 = d[4][nt][ri];
                            float Yw0 = d[5][nt][ri], Yw1 = d[6][nt][ri], Yw2 = d[7][nt][ri];
                            sr[cc] = O0 + bias_s[cc];
                            sr[64 + 3 * cc + 0] = C1F * fmaf(v0, Ysv, x2s * Yv0);
                            sr[64 + 3 * cc + 1] = C1F * fmaf(v1, Ysv, x2s * Yv1);
                            sr[64 + 3 * cc + 2] = C1F * fmaf(v2, Ysv, x2s * Yv2);
                            sr[256 + 3 * cc + 0] = C2F * (Yw1 * v2 - Yw2 * v1);
                            sr[256 + 3 * cc + 1] = C2F * (Yw2 * v0 - Yw0 * v2);
                            sr[256 + 3 * cc + 2] = C2F * (Yw0 * v1 - Yw1 * v0);
                        }
                    }
                }
            }
            __syncthreads();
            // coalesced copy-out: 32 rows x 448 f32
            #pragma unroll
            for (int i = 0; i < 7; i++) {
                int f = i * THREADS + tid;               // < 3584
                int r = f / 112, j = (f % 112) * 4;
                float4 v = *(const float4*)(stg + r * STG_STRIDE + j);
                int rg = row0 + 32 * half + r;
                if (rg < nrows) *(float4*)(out + (size_t)rg * 448 + j) = v;
            }
            __syncthreads();
        }
    }
}

extern "C" void kernel_launch(void* const* d_in, const int* in_sizes, int n_in,
                              void* d_out, int out_size)
{
    const float* x1    = (const float*)d_in[0];
    const float* x2    = (const float*)d_in[1];
    const float* w_ss  = (const float*)d_in[2];
    const float* w_vv0 = (const float*)d_in[3];
    const float* w_sv  = (const float*)d_in[4];
    const float* w_vs  = (const float*)d_in[5];
    const float* w_vv1 = (const float*)d_in[6];
    const float* bias  = (const float*)d_in[7];

    int nrows = in_sizes[0] / 256;
    int ntiles = (nrows + TILE_M - 1) / TILE_M;

    cudaFuncSetAttribute(o3tp_mma2_kernel, cudaFuncAttributeMaxDynamicSharedMemorySize, SM_TOTAL);

    int sm_count = 148;
    cudaDeviceGetAttribute(&sm_count, cudaDevAttrMultiProcessorCount, 0);
    int grid = sm_count < ntiles ? sm_count : ntiles;
    if (grid < 1) grid = 1;

    o3tp_mma2_kernel<<<grid, THREADS, SM_TOTAL>>>(
        x1, x2, w_ss, w_vv0, w_sv, w_vs, w_vv1, bias, (float*)d_out, nrows);
}

// round 7
// speedup vs baseline: 2.1741x; 1.1677x over previous
#include <cuda_runtime.h>
#include <cuda_fp16.h>
#include <cstdint>

#define THREADS 512
#define TILE_M 64

// ---- folded constants ----
#define PW0F 0.08838834764831845f   // sqrt(1/128)
#define C0BF 0.05103103630798288f   // PW0/sqrt(3)
#define C1F  0.08838834764831845f   // sqrt(3/128)/sqrt(3) = PW0
#define C2F  0.7071067811865476f    // sqrt(3/64)/sqrt(6)*8 = 1/sqrt(2)

// ---- smem layout (byte offsets) ----
// Weights: 5 tiles (fp16, single precision level), each [64k x 64n], 128B rows, swizzled.
//   order: 0=Wss 1=Wvv0 2=Wsv 3=Wvs 4=Wvv1
// A: 12 buffers (6 channels x hi/lo fp16), each [64r x 64k] = 8192B.
//   channels: 0=PW0*x2s*xs  1=C0B*dot  2=xs  3=a0  4=a1  5=a2
// Stage (epilogue, 32 rows x 452 f32 = 57856B) overlaps the A region.
#define SM_W     0
#define SM_A     40960
#define SM_X2    139264     // 64 * float4
#define SM_BIAS  140288     // 64 * f32
#define SM_TOTAL 140544
#define STG_STRIDE 452

#define SWZ(o) ((o) ^ (((o) >> 3) & 0x70))

// ================= helpers =================
static __device__ __forceinline__ uint32_t smem_u32(const void* p) {
    uint32_t a;
    asm("{ .reg .u64 t; cvta.to.shared.u64 t, %1; cvt.u32.u64 %0, t; }" : "=r"(a) : "l"(p));
    return a;
}
static __device__ __forceinline__ void ldsm4(uint32_t* r, uint32_t addr) {
    asm volatile("ldmatrix.sync.aligned.m8n8.x4.shared.b16 {%0,%1,%2,%3}, [%4];"
                 : "=r"(r[0]), "=r"(r[1]), "=r"(r[2]), "=r"(r[3]) : "r"(addr));
}
static __device__ __forceinline__ void ldsm4t(uint32_t* r, uint32_t addr) {
    asm volatile("ldmatrix.sync.aligned.m8n8.x4.trans.shared.b16 {%0,%1,%2,%3}, [%4];"
                 : "=r"(r[0]), "=r"(r[1]), "=r"(r[2]), "=r"(r[3]) : "r"(addr));
}
static __device__ __forceinline__ void mma16816h(float* d, const uint32_t* a, uint32_t b0, uint32_t b1) {
    asm volatile("mma.sync.aligned.m16n8k16.row.col.f32.f16.f16.f32 "
                 "{%0,%1,%2,%3}, {%4,%5,%6,%7}, {%8,%9}, {%0,%1,%2,%3};"
                 : "+f"(d[0]), "+f"(d[1]), "+f"(d[2]), "+f"(d[3])
                 : "r"(a[0]), "r"(a[1]), "r"(a[2]), "r"(a[3]), "r"(b0), "r"(b1));
}
// 2-pass fp16 split-A product accumulate into d[2][4] (two n8 tiles)
static __device__ __forceinline__ void dualmma(float d[2][4], const uint32_t* ah, const uint32_t* al,
                                               const uint32_t* Bh) {
    #pragma unroll
    for (int nb = 0; nb < 2; nb++) {
        mma16816h(d[nb], ah, Bh[2 * nb], Bh[2 * nb + 1]);
        mma16816h(d[nb], al, Bh[2 * nb], Bh[2 * nb + 1]);
    }
}
// split fp32 pair -> fp16 hi/lo at swizzled offset
static __device__ __forceinline__ void put_pair(char* smem, uint32_t hi_off, uint32_t lo_off,
                                                uint32_t off, float v0, float v1) {
    __half h0 = __float2half_rn(v0);
    __half h1 = __float2half_rn(v1);
    __half l0 = __float2half_rn(v0 - __half2float(h0));
    __half l1 = __float2half_rn(v1 - __half2float(h1));
    uint32_t hp = (uint32_t)__half_as_ushort(h0) | ((uint32_t)__half_as_ushort(h1) << 16);
    uint32_t lp = (uint32_t)__half_as_ushort(l0) | ((uint32_t)__half_as_ushort(l1) << 16);
    uint32_t so = SWZ(off);
    *(uint32_t*)(smem + hi_off + so) = hp;
    *(uint32_t*)(smem + lo_off + so) = lp;
}
// single fp16 pair store (weights)
static __device__ __forceinline__ void put_w(char* smem, uint32_t base, uint32_t off, float v0, float v1) {
    __half h0 = __float2half_rn(v0);
    __half h1 = __float2half_rn(v1);
    uint32_t hp = (uint32_t)__half_as_ushort(h0) | ((uint32_t)__half_as_ushort(h1) << 16);
    *(uint32_t*)(smem + base + SWZ(off)) = hp;
}

__global__ __launch_bounds__(THREADS, 1)
void o3tp_mma3_kernel(const float* __restrict__ x1, const float* __restrict__ x2,
                      const float* __restrict__ w_ss, const float* __restrict__ w_vv0,
                      const float* __restrict__ w_sv, const float* __restrict__ w_vs,
                      const float* __restrict__ w_vv1, const float* __restrict__ bias,
                      float* __restrict__ out, int nrows)
{
    extern __shared__ char smem[];
    const int tid = threadIdx.x;
    const int lane = tid & 31;
    const int wid = tid >> 5;
    const int rq = wid & 3;        // row block: rows 16*rq .. +16 (of 64)
    const int nh = wid >> 2;       // col block: cols 16*nh .. +16
    const uint32_t smb = smem_u32(smem);

    // ---- weight prep: [k][n] fp16, swizzled ----
    {
        const float* wsrc[5] = { w_ss, w_vv0, w_sv, w_vs, w_vv1 };
        #pragma unroll
        for (int m = 0; m < 5; m++) {
            uint32_t base = SM_W + (uint32_t)m * 8192;
            #pragma unroll
            for (int it = 0; it < 4; it++) {
                int idx = it * THREADS + tid;         // 0..2047
                int k = idx >> 5, np = idx & 31;
                float2 w2 = *(const float2*)(wsrc[m] + k * 64 + 2 * np);
                put_w(smem, base, (uint32_t)(k * 128 + np * 4), w2.x, w2.y);
            }
        }
        if (tid < 64) *(float*)(smem + SM_BIAS + tid * 4) = bias[tid];
    }
    __syncthreads();

    // ---- per-lane constant address pieces ----
    const int t4 = lane >> 3;
    const int arow = 16 * rq + ((t4 & 1) << 3) + (lane & 7);
    const uint32_t a_rb  = (uint32_t)arow * 128;
    const uint32_t a_kx  = (uint32_t)(arow & 7) << 4;
    const uint32_t a_kb0 = (uint32_t)(t4 >> 1) << 4;
    const int brow_l = ((t4 & 1) << 3) + (lane & 7);
    const uint32_t b_cb = (uint32_t)(2 * (16 * nh + ((t4 >> 1) << 3)));
    const uint32_t b_kx = (uint32_t)(lane & 7) << 4;

    const int ntiles = (nrows + TILE_M - 1) / TILE_M;
    const int g = lane >> 2, tq = lane & 3;
    float* stg = (float*)(smem + SM_A);               // stage overlaps A region
    const float* bias_s = (const float*)(smem + SM_BIAS);

    for (int tile = blockIdx.x; tile < ntiles; tile += gridDim.x) {
        const int row0 = tile * TILE_M;

        // ---- L2 prefetch next tile's x1 (1 cache line per thread) ----
        {
            int tnext = tile + gridDim.x;
            if (tnext < ntiles) {
                int r = tnext * TILE_M + (tid >> 3);
                if (r < nrows) {
                    const float* p = x1 + (size_t)r * 256 + (tid & 7) * 32;
                    asm volatile("prefetch.global.L2 [%0];" :: "l"(p));
                }
            }
        }

        // ---- stage x2 rows ----
        if (tid < 64) {
            int rg = row0 + tid; if (rg >= nrows) rg = nrows - 1;
            *(float4*)(smem + SM_X2 + tid * 16) = *(const float4*)(x2 + (size_t)4 * rg);
        }
        __syncthreads();   // build consumes SM_X2

        // ---- build 6 A channels, fp16 hi/lo ----
        #pragma unroll
        for (int it = 0; it < 4; it++) {
            int idx = it * THREADS + tid;            // 0..2047
            int row = idx >> 5, kp = idx & 31;
            int rg = row0 + row; if (rg >= nrows) rg = nrows - 1;
            const float* xr = x1 + (size_t)rg * 256;
            float2 xs = *(const float2*)(xr + 2 * kp);
            float2 f0 = *(const float2*)(xr + 64 + 6 * kp);
            float2 f1 = *(const float2*)(xr + 66 + 6 * kp);
            float2 f2 = *(const float2*)(xr + 68 + 6 * kp);
            float4 q = *(const float4*)(smem + SM_X2 + row * 16);
            uint32_t off = (uint32_t)(row * 128 + kp * 4);
            // ch0: pre-gated scalar path
            float sc = PW0F * q.x;
            put_pair(smem, SM_A + 0 * 8192, SM_A + 1 * 8192, off, sc * xs.x, sc * xs.y);
            // ch1: pre-gated dot channel
            float d0 = fmaf(f0.x, q.y, fmaf(f0.y, q.z, f1.x * q.w));
            float d1 = fmaf(f1.y, q.y, fmaf(f2.x, q.z, f2.y * q.w));
            put_pair(smem, SM_A + 2 * 8192, SM_A + 3 * 8192, off, C0BF * d0, C0BF * d1);
            // ch2: raw xs ; ch3-5: a components (k, k+1)
            put_pair(smem, SM_A + 4 * 8192,  SM_A + 5 * 8192,  off, xs.x, xs.y);
            put_pair(smem, SM_A + 6 * 8192,  SM_A + 7 * 8192,  off, f0.x, f1.y);
            put_pair(smem, SM_A + 8 * 8192,  SM_A + 9 * 8192,  off, f0.y, f2.x);
            put_pair(smem, SM_A + 10 * 8192, SM_A + 11 * 8192, off, f1.x, f2.y);
        }
        __syncthreads();

        // ---- GEMMs: d0=out0(merged) d1=Ysv d2-4=Yv_i(@Wvs) d5-7=Yw_i(@Wvv1) ----
        float d[8][2][4];
        #pragma unroll
        for (int q8 = 0; q8 < 8; q8++)
            #pragma unroll
            for (int nb = 0; nb < 2; nb++)
                #pragma unroll
                for (int e = 0; e < 4; e++) d[q8][nb][e] = 0.0f;

        #pragma unroll
        for (int ks = 0; ks < 4; ks++) {
            const uint32_t a_koff = (32u * ks + a_kb0) ^ a_kx;
            const uint32_t b_base = (uint32_t)(16 * ks + brow_l) * 128 + (b_cb ^ b_kx);
            uint32_t Ah[4], Al[4], Bh[4];

            // ch0 @ Wss -> d0
            {
                uint32_t ab = smb + SM_A + 0 * 8192 + a_rb + a_koff;
                ldsm4(Ah, ab); ldsm4(Al, ab + 8192);
                ldsm4t(Bh, smb + SM_W + 0 * 8192 + b_base);
                dualmma(d[0], Ah, Al, Bh);
            }
            // ch1 @ Wvv0 -> d0
            {
                uint32_t ab = smb + SM_A + 2 * 8192 + a_rb + a_koff;
                ldsm4(Ah, ab); ldsm4(Al, ab + 8192);
                ldsm4t(Bh, smb + SM_W + 1 * 8192 + b_base);
                dualmma(d[0], Ah, Al, Bh);
            }
            // ch2 @ Wsv -> d1
            {
                uint32_t ab = smb + SM_A + 4 * 8192 + a_rb + a_koff;
                ldsm4(Ah, ab); ldsm4(Al, ab + 8192);
                ldsm4t(Bh, smb + SM_W + 2 * 8192 + b_base);
                dualmma(d[1], Ah, Al, Bh);
            }
            // hold Wvs / Wvv1 frags, loop a-channels
            uint32_t Vh[4], Wh[4];
            ldsm4t(Vh, smb + SM_W + 3 * 8192 + b_base);
            ldsm4t(Wh, smb + SM_W + 4 * 8192 + b_base);
            #pragma unroll
            for (int j = 0; j < 3; j++) {
                uint32_t ab = smb + SM_A + (uint32_t)(6 + 2 * j) * 8192 + a_rb + a_koff;
                ldsm4(Ah, ab); ldsm4(Al, ab + 8192);
                dualmma(d[2 + j], Ah, Al, Vh);
                dualmma(d[5 + j], Ah, Al, Wh);
            }
        }
        __syncthreads();   // A reads done; stage region reusable

        // ---- epilogue in two 32-row halves (stage overlaps A) ----
        #pragma unroll 1
        for (int half = 0; half < 2; half++) {
            if ((rq >> 1) == half) {
                #pragma unroll
                for (int hh = 0; hh < 2; hh++) {
                    int rl = 16 * (rq & 1) + g + 8 * hh;          // 0..31 local
                    int rt = 32 * half + rl;                       // 0..63 in tile
                    float4 q = *(const float4*)(smem + SM_X2 + rt * 16);
                    float x2s = q.x, v0 = q.y, v1 = q.z, v2 = q.w;
                    float* sr = stg + rl * STG_STRIDE;
                    #pragma unroll
                    for (int nt = 0; nt < 2; nt++) {
                        #pragma unroll
                        for (int e = 0; e < 2; e++) {
                            int cc = 16 * nh + 8 * nt + 2 * tq + e;
                            int ri = 2 * hh + e;
                            float O0  = d[0][nt][ri];
                            float Ysv = d[1][nt][ri];
                            float Yv0 = d[2][nt][ri], Yv1 = d[3][nt][ri], Yv2 = d[4][nt][ri];
                            float Yw0 = d[5][nt][ri], Yw1 = d[6][nt][ri], Yw2 = d[7][nt][ri];
                            sr[cc] = O0 + bias_s[cc];
                            sr[64 + 3 * cc + 0] = C1F * fmaf(v0, Ysv, x2s * Yv0);
                            sr[64 + 3 * cc + 1] = C1F * fmaf(v1, Ysv, x2s * Yv1);
                            sr[64 + 3 * cc + 2] = C1F * fmaf(v2, Ysv, x2s * Yv2);
                            sr[256 + 3 * cc + 0] = C2F * (Yw1 * v2 - Yw2 * v1);
                            sr[256 + 3 * cc + 1] = C2F * (Yw2 * v0 - Yw0 * v2);
                            sr[256 + 3 * cc + 2] = C2F * (Yw0 * v1 - Yw1 * v0);
                        }
                    }
                }
            }
            __syncthreads();
            // coalesced copy-out: 32 rows x 448 f32
            #pragma unroll
            for (int i = 0; i < 7; i++) {
                int f = i * THREADS + tid;               // < 3584
                int r = f / 112, j = (f % 112) * 4;
                float4 v = *(const float4*)(stg + r * STG_STRIDE + j);
                int rg = row0 + 32 * half + r;
                if (rg < nrows) *(float4*)(out + (size_t)rg * 448 + j) = v;
            }
            __syncthreads();
        }
    }
}

extern "C" void kernel_launch(void* const* d_in, const int* in_sizes, int n_in,
                              void* d_out, int out_size)
{
    const float* x1    = (const float*)d_in[0];
    const float* x2    = (const float*)d_in[1];
    const float* w_ss  = (const float*)d_in[2];
    const float* w_vv0 = (const float*)d_in[3];
    const float* w_sv  = (const float*)d_in[4];
    const float* w_vs  = (const float*)d_in[5];
    const float* w_vv1 = (const float*)d_in[6];
    const float* bias  = (const float*)d_in[7];

    int nrows = in_sizes[0] / 256;
    int ntiles = (nrows + TILE_M - 1) / TILE_M;

    cudaFuncSetAttribute(o3tp_mma3_kernel, cudaFuncAttributeMaxDynamicSharedMemorySize, SM_TOTAL);

    int sm_count = 148;
    cudaDeviceGetAttribute(&sm_count, cudaDevAttrMultiProcessorCount, 0);
    int grid = sm_count < ntiles ? sm_count : ntiles;
    if (grid < 1) grid = 1;

    o3tp_mma3_kernel<<<grid, THREADS, SM_TOTAL>>>(
        x1, x2, w_ss, w_vv0, w_sv, w_vs, w_vv1, bias, (float*)d_out, nrows);
}

// round 8
// speedup vs baseline: 3.2862x; 1.5115x over previous
#include <cuda_runtime.h>
#include <cuda_fp16.h>
#include <cstdint>

#define THREADS 256
#define TILE_M 32

// ---- folded constants ----
#define PW0F 0.08838834764831845f   // sqrt(1/128)
#define C0BF 0.05103103630798288f   // PW0/sqrt(3)
#define C1F  0.08838834764831845f   // sqrt(3/128)/sqrt(3) = PW0
#define C2F  0.7071067811865476f    // sqrt(3/64)/sqrt(6)*8 = 1/sqrt(2)

// ---- smem layout (byte offsets), ~95 KB -> 2 CTAs / SM ----
// Weights: 5 fp16 tiles [64k x 64n], 128B rows, swizzled. 0=Wss 1=Wvv0 2=Wsv 3=Wvs 4=Wvv1
// A: 6 fp16 buffers [32r x 64k] = 4096B each. ch: 0=PW0*x2s*xs 1=C0B*dot 2=xs 3=a0 4=a1 5=a2
// Stage: 16 rows x 452 f32 (epilogue half-tile)
#define SM_W     0
#define SM_A     40960
#define SM_STG   65536
#define SM_X2    94464      // 32 * float4
#define SM_BIAS  94976      // 64 * f32
#define SM_TOTAL 95232
#define STG_STRIDE 452

#define SWZ(o) ((o) ^ (((o) >> 3) & 0x70))

// ================= helpers =================
static __device__ __forceinline__ uint32_t smem_u32(const void* p) {
    uint32_t a;
    asm("{ .reg .u64 t; cvta.to.shared.u64 t, %1; cvt.u32.u64 %0, t; }" : "=r"(a) : "l"(p));
    return a;
}
static __device__ __forceinline__ void ldsm4(uint32_t* r, uint32_t addr) {
    asm volatile("ldmatrix.sync.aligned.m8n8.x4.shared.b16 {%0,%1,%2,%3}, [%4];"
                 : "=r"(r[0]), "=r"(r[1]), "=r"(r[2]), "=r"(r[3]) : "r"(addr));
}
static __device__ __forceinline__ void ldsm4t(uint32_t* r, uint32_t addr) {
    asm volatile("ldmatrix.sync.aligned.m8n8.x4.trans.shared.b16 {%0,%1,%2,%3}, [%4];"
                 : "=r"(r[0]), "=r"(r[1]), "=r"(r[2]), "=r"(r[3]) : "r"(addr));
}
static __device__ __forceinline__ void mma16816h(float* d, const uint32_t* a, uint32_t b0, uint32_t b1) {
    asm volatile("mma.sync.aligned.m16n8k16.row.col.f32.f16.f16.f32 "
                 "{%0,%1,%2,%3}, {%4,%5,%6,%7}, {%8,%9}, {%0,%1,%2,%3};"
                 : "+f"(d[0]), "+f"(d[1]), "+f"(d[2]), "+f"(d[3])
                 : "r"(a[0]), "r"(a[1]), "r"(a[2]), "r"(a[3]), "r"(b0), "r"(b1));
}
static __device__ __forceinline__ void dualmma(float d[2][4], const uint32_t* a, const uint32_t* B) {
    #pragma unroll
    for (int nb = 0; nb < 2; nb++)
        mma16816h(d[nb], a, B[2 * nb], B[2 * nb + 1]);
}
// fp32 pair -> packed fp16 at swizzled offset
static __device__ __forceinline__ void put_h(char* smem, uint32_t base, uint32_t off, float v0, float v1) {
    __half h0 = __float2half_rn(v0);
    __half h1 = __float2half_rn(v1);
    uint32_t hp = (uint32_t)__half_as_ushort(h0) | ((uint32_t)__half_as_ushort(h1) << 16);
    *(uint32_t*)(smem + base + SWZ(off)) = hp;
}

__global__ __launch_bounds__(THREADS, 2)
void o3tp_mma4_kernel(const float* __restrict__ x1, const float* __restrict__ x2,
                      const float* __restrict__ w_ss, const float* __restrict__ w_vv0,
                      const float* __restrict__ w_sv, const float* __restrict__ w_vs,
                      const float* __restrict__ w_vv1, const float* __restrict__ bias,
                      float* __restrict__ out, int nrows)
{
    extern __shared__ char smem[];
    const int tid = threadIdx.x;
    const int lane = tid & 31;
    const int wid = tid >> 5;
    const int rq = wid & 1;        // row block: rows 16*rq .. +16 (of 32)
    const int nh = wid >> 1;       // col block: cols 16*nh .. +16
    const uint32_t smb = smem_u32(smem);

    // ---- weight prep: [k][n] fp16, swizzled ----
    {
        const float* wsrc[5] = { w_ss, w_vv0, w_sv, w_vs, w_vv1 };
        #pragma unroll
        for (int m = 0; m < 5; m++) {
            uint32_t base = SM_W + (uint32_t)m * 8192;
            #pragma unroll
            for (int it = 0; it < 8; it++) {
                int idx = it * THREADS + tid;         // 0..2047
                int k = idx >> 5, np = idx & 31;
                float2 w2 = *(const float2*)(wsrc[m] + k * 64 + 2 * np);
                put_h(smem, base, (uint32_t)(k * 128 + np * 4), w2.x, w2.y);
            }
        }
        if (tid < 64) *(float*)(smem + SM_BIAS + tid * 4) = bias[tid];
    }
    __syncthreads();

    // ---- per-lane constant address pieces ----
    const int t4 = lane >> 3;
    const int arow = 16 * rq + ((t4 & 1) << 3) + (lane & 7);       // 0..31
    const uint32_t a_rb  = (uint32_t)arow * 128;
    const uint32_t a_kx  = (uint32_t)(arow & 7) << 4;
    const uint32_t a_kb0 = (uint32_t)(t4 >> 1) << 4;
    const int brow_l = ((t4 & 1) << 3) + (lane & 7);
    const uint32_t b_cb = (uint32_t)(2 * (16 * nh + ((t4 >> 1) << 3)));
    const uint32_t b_kx = (uint32_t)(lane & 7) << 4;

    const int ntiles = (nrows + TILE_M - 1) / TILE_M;
    const int g = lane >> 2, tq = lane & 3;
    float* stg = (float*)(smem + SM_STG);
    const float* bias_s = (const float*)(smem + SM_BIAS);

    for (int tile = blockIdx.x; tile < ntiles; tile += gridDim.x) {
        const int row0 = tile * TILE_M;

        // ---- L2 prefetch next tile's x1 ----
        {
            int tnext = tile + gridDim.x;
            if (tnext < ntiles) {
                int r = tnext * TILE_M + (tid >> 3);
                if (r < nrows) {
                    const float* p = x1 + (size_t)r * 256 + (tid & 7) * 32;
                    asm volatile("prefetch.global.L2 [%0];" :: "l"(p));
                }
            }
        }

        // ---- stage x2 rows ----
        if (tid < 32) {
            int rg = row0 + tid; if (rg >= nrows) rg = nrows - 1;
            *(float4*)(smem + SM_X2 + tid * 16) = *(const float4*)(x2 + (size_t)4 * rg);
        }
        __syncthreads();

        // ---- build 6 A channels, fp16 ----
        #pragma unroll
        for (int it = 0; it < 4; it++) {
            int idx = it * THREADS + tid;            // 0..1023
            int row = idx >> 5, kp = idx & 31;
            int rg = row0 + row; if (rg >= nrows) rg = nrows - 1;
            const float* xr = x1 + (size_t)rg * 256;
            float2 xs = *(const float2*)(xr + 2 * kp);
            float2 f0 = *(const float2*)(xr + 64 + 6 * kp);
            float2 f1 = *(const float2*)(xr + 66 + 6 * kp);
            float2 f2 = *(const float2*)(xr + 68 + 6 * kp);
            float4 q = *(const float4*)(smem + SM_X2 + row * 16);
            uint32_t off = (uint32_t)(row * 128 + kp * 4);
            float sc = PW0F * q.x;
            put_h(smem, SM_A + 0 * 4096, off, sc * xs.x, sc * xs.y);
            float d0 = fmaf(f0.x, q.y, fmaf(f0.y, q.z, f1.x * q.w));
            float d1 = fmaf(f1.y, q.y, fmaf(f2.x, q.z, f2.y * q.w));
            put_h(smem, SM_A + 1 * 4096, off, C0BF * d0, C0BF * d1);
            put_h(smem, SM_A + 2 * 4096, off, xs.x, xs.y);
            put_h(smem, SM_A + 3 * 4096, off, f0.x, f1.y);
            put_h(smem, SM_A + 4 * 4096, off, f0.y, f2.x);
            put_h(smem, SM_A + 5 * 4096, off, f1.x, f2.y);
        }
        __syncthreads();

        // ---- GEMMs: d0=out0(merged) d1=Ysv d2-4=Yv_i(@Wvs) d5-7=Yw_i(@Wvv1) ----
        float d[8][2][4];
        #pragma unroll
        for (int q8 = 0; q8 < 8; q8++)
            #pragma unroll
            for (int nb = 0; nb < 2; nb++)
                #pragma unroll
                for (int e = 0; e < 4; e++) d[q8][nb][e] = 0.0f;

        #pragma unroll
        for (int ks = 0; ks < 4; ks++) {
            const uint32_t a_koff = (32u * ks + a_kb0) ^ a_kx;
            const uint32_t b_base = (uint32_t)(16 * ks + brow_l) * 128 + (b_cb ^ b_kx);
            uint32_t Ax[4], Bh[4];

            ldsm4(Ax, smb + SM_A + 0 * 4096 + a_rb + a_koff);
            ldsm4t(Bh, smb + SM_W + 0 * 8192 + b_base);
            dualmma(d[0], Ax, Bh);

            ldsm4(Ax, smb + SM_A + 1 * 4096 + a_rb + a_koff);
            ldsm4t(Bh, smb + SM_W + 1 * 8192 + b_base);
            dualmma(d[0], Ax, Bh);

            ldsm4(Ax, smb + SM_A + 2 * 4096 + a_rb + a_koff);
            ldsm4t(Bh, smb + SM_W + 2 * 8192 + b_base);
            dualmma(d[1], Ax, Bh);

            uint32_t Vh[4], Wh[4];
            ldsm4t(Vh, smb + SM_W + 3 * 8192 + b_base);
            ldsm4t(Wh, smb + SM_W + 4 * 8192 + b_base);
            #pragma unroll
            for (int j = 0; j < 3; j++) {
                ldsm4(Ax, smb + SM_A + (uint32_t)(3 + j) * 4096 + a_rb + a_koff);
                dualmma(d[2 + j], Ax, Vh);
                dualmma(d[5 + j], Ax, Wh);
            }
        }

        // ---- epilogue in two 16-row halves ----
        #pragma unroll 1
        for (int half = 0; half < 2; half++) {
            if (rq == half) {
                #pragma unroll
                for (int hh = 0; hh < 2; hh++) {
                    int rl = g + 8 * hh;                           // 0..15 local
                    int rt = 16 * half + rl;                       // 0..31 in tile
                    float4 q = *(const float4*)(smem + SM_X2 + rt * 16);
                    float x2s = q.x, v0 = q.y, v1 = q.z, v2 = q.w;
                    float* sr = stg + rl * STG_STRIDE;
                    #pragma unroll
                    for (int nt = 0; nt < 2; nt++) {
                        #pragma unroll
                        for (int e = 0; e < 2; e++) {
                            int cc = 16 * nh + 8 * nt + 2 * tq + e;
                            int ri = 2 * hh + e;
                            float O0  = d[0][nt][ri];
                            float Ysv = d[1][nt][ri];
                            float Yv0 = d[2][nt][ri], Yv1 = d[3][nt][ri], Yv2 = d[4][nt][ri];
                            float Yw0 = d[5][nt][ri], Yw1 = d[6][nt][ri], Yw2 = d[7][nt][ri];
                            sr[cc] = O0 + bias_s[cc];
                            sr[64 + 3 * cc + 0] = C1F * fmaf(v0, Ysv, x2s * Yv0);
                            sr[64 + 3 * cc + 1] = C1F * fmaf(v1, Ysv, x2s * Yv1);
                            sr[64 + 3 * cc + 2] = C1F * fmaf(v2, Ysv, x2s * Yv2);
                            sr[256 + 3 * cc + 0] = C2F * (Yw1 * v2 - Yw2 * v1);
                            sr[256 + 3 * cc + 1] = C2F * (Yw2 * v0 - Yw0 * v2);
                            sr[256 + 3 * cc + 2] = C2F * (Yw0 * v1 - Yw1 * v0);
                        }
                    }
                }
            }
            __syncthreads();
            // coalesced copy-out: 16 rows x 448 f32
            #pragma unroll
            for (int i = 0; i < 7; i++) {
                int f = i * THREADS + tid;               // < 1792
                int r = f / 112, j = (f % 112) * 4;
                float4 v = *(const float4*)(stg + r * STG_STRIDE + j);
                int rg = row0 + 16 * half + r;
                if (rg < nrows) *(float4*)(out + (size_t)rg * 448 + j) = v;
            }
            __syncthreads();
        }
    }
}

extern "C" void kernel_launch(void* const* d_in, const int* in_sizes, int n_in,
                              void* d_out, int out_size)
{
    const float* x1    = (const float*)d_in[0];
    const float* x2    = (const float*)d_in[1];
    const float* w_ss  = (const float*)d_in[2];
    const float* w_vv0 = (const float*)d_in[3];
    const float* w_sv  = (const float*)d_in[4];
    const float* w_vs  = (const float*)d_in[5];
    const float* w_vv1 = (const float*)d_in[6];
    const float* bias  = (const float*)d_in[7];

    int nrows = in_sizes[0] / 256;
    int ntiles = (nrows + TILE_M - 1) / TILE_M;

    cudaFuncSetAttribute(o3tp_mma4_kernel, cudaFuncAttributeMaxDynamicSharedMemorySize, SM_TOTAL);

    int sm_count = 148;
    cudaDeviceGetAttribute(&sm_count, cudaDevAttrMultiProcessorCount, 0);
    int grid = 2 * sm_count;
    if (grid > ntiles) grid = ntiles;
    if (grid < 1) grid = 1;

    o3tp_mma4_kernel<<<grid, THREADS, SM_TOTAL>>>(
        x1, x2, w_ss, w_vv0, w_sv, w_vs, w_vv1, bias, (float*)d_out, nrows);
}